// round 13
// baseline (speedup 1.0000x reference)
#include <cuda_runtime.h>
#include <cuda_fp16.h>
#include <cstdint>

#define H 512
#define W 512
#define HW (H*W)
#define NB 2
#define NC 21
#define NCC 11           // global channel pairs (ch20 + pad)
#define NCCS 12          // smem channel pairs (extra zero pad plane)
#define NPIX (NB*HW)
#define NTAP 25
#define NBHW (NB*HW)

// q buffers: pair-planar layout [b][y][cc][x][2] fp32; coefs planar fp16
__device__ float  g_qA[(size_t)NB*H*NCC*W*2];
__device__ float  g_qB[(size_t)NB*H*NCC*W*2];
__device__ __half g_wch[NTAP*NB*HW];

__device__ __forceinline__ int reflect_idx(int i, int n) {
    if (i < 0) i = -i;
    if (i >= n) i = 2*n - 2 - i;
    return i;
}

__device__ __forceinline__ unsigned long long pk2(float lo, float hi) {
    unsigned long long r;
    asm("mov.b64 %0, {%1, %2};" : "=l"(r) : "f"(lo), "f"(hi));
    return r;
}
__device__ __forceinline__ void upk2(float& lo, float& hi, unsigned long long v) {
    asm("mov.b64 {%0, %1}, %2;" : "=f"(lo), "=f"(hi) : "l"(v));
}
#define FMA2(acc, a, b) \
    asm("fma.rn.f32x2 %0, %1, %2, %0;" : "+l"(acc) : "l"(a), "l"(b))
#define MUL2(out, a, b) \
    asm("mul.rn.f32x2 %0, %1, %2;" : "=l"(out) : "l"(a), "l"(b))

// ---------------------------------------------------------------------------
// Kernel 1: q0 = softmax(unary), written pair-planar
// ---------------------------------------------------------------------------
__global__ void __launch_bounds__(256) init_softmax(const float* __restrict__ unary,
                                                    float* __restrict__ q) {
    int idx = blockIdx.x * 256 + threadIdx.x;
    if (idx >= NPIX) return;
    int b = idx / HW, pix = idx % HW;
    int y = pix / W, x = pix % W;
    const float* u = unary + (size_t)b * NC * HW + pix;
    float e[NC];
    float s = 0.f;
#pragma unroll
    for (int c = 0; c < NC; c++) { e[c] = __expf(u[c*HW]); s += e[c]; }
    float inv = 1.f / s;
    float* qr = q + ((size_t)(b*H + y)*NCC)*(W*2) + x*2;
#pragma unroll
    for (int cc = 0; cc < 10; cc++) {
        float2 v; v.x = e[2*cc]*inv; v.y = e[2*cc+1]*inv;
        *reinterpret_cast<float2*>(qr + cc*(W*2)) = v;
    }
    float2 v10; v10.x = e[20]*inv; v10.y = 0.f;
    *reinterpret_cast<float2*>(qr + 10*(W*2)) = v10;
}

// ---------------------------------------------------------------------------
// Kernel 2: combined coefficients (fp16, planar SoA [tap][b][y][x])
// ---------------------------------------------------------------------------
__global__ void __launch_bounds__(256) compute_weights(const float* __restrict__ image,
                                                       const float* __restrict__ edges) {
    __shared__ float sg[4][12][36];
    int tx = threadIdx.x, ty = threadIdx.y;
    int b = blockIdx.z;
    int x0 = blockIdx.x * 32, y0 = blockIdx.y * 8;
    int tid = ty * 32 + tx;

    for (int idx = tid; idx < 4*12*36; idx += 256) {
        int ch = idx / (12*36);
        int r  = idx % (12*36);
        int ry = r / 36, sx = r % 36;
        int gy = reflect_idx(y0 + ry - 2, H);
        int gx = reflect_idx(x0 + sx - 2, W);
        float v;
        if (ch < 3) v = image[((size_t)(b*3 + ch))*HW + gy*W + gx];
        else        v = edges[(size_t)b*HW + gy*W + gx];
        sg[ch][ry][sx] = v;
    }
    __syncthreads();

    float sp[5], g2[5];
    {
        float s = 0.f;
#pragma unroll
        for (int i = 0; i < 5; i++) {
            float x = (float)(i - 2);
            sp[i] = __expf(-x*x * 0.02f);
            float g = __expf(-2.f * x*x);
            g2[i] = g; s += g;
        }
        float inv = 1.f / s;
#pragma unroll
        for (int i = 0; i < 5; i++) g2[i] *= inv;
    }

    int ry = ty + 2, rx = tx + 2;
    float cr = sg[0][ry][rx], cg = sg[1][ry][rx], cb = sg[2][ry][rx], ce = sg[3][ry][rx];

    float wr[NTAP], we[NTAP];
    float sr = 0.f, se = 0.f;
#pragma unroll
    for (int dy = 0; dy < 5; dy++) {
#pragma unroll
        for (int dx = 0; dx < 5; dx++) {
            int t = dy*5 + dx;
            float d = fabsf(sg[0][ry+dy-2][rx+dx-2] - cr)
                    + fabsf(sg[1][ry+dy-2][rx+dx-2] - cg)
                    + fabsf(sg[2][ry+dy-2][rx+dx-2] - cb);
            float s2 = sp[dy] * sp[dx];
            float w  = s2 * __expf(-2.f * d * d);
            wr[t] = w; sr += w;
            float de = fabsf(sg[3][ry+dy-2][rx+dx-2] - ce);
            float w2 = s2 * __expf(-2.f * de * de);
            we[t] = w2; se += w2;
        }
    }
    float isr = 1.f / sr, ise = 1.f / se;
    int pix = b*HW + (y0 + ty)*W + (x0 + tx);
#pragma unroll
    for (int dy = 0; dy < 5; dy++) {
#pragma unroll
        for (int dx = 0; dx < 5; dx++) {
            int t = dy*5 + dx;
            g_wch[t*(NB*HW) + pix] = __float2half(g2[dy]*g2[dx] + wr[t]*isr + we[t]*ise);
        }
    }
}

// ---------------------------------------------------------------------------
// Kernel 3: one CRF iteration.
// Tile 64x8, block (32,8)=256 thr, 2 CTAs/SM.
// Per thread: 2 px (tx) x 2 adjacent rows (r=ty&3) x 6 cc (h=ty>>2).
// The 6-row smem window is shared between the two output rows: LDS/output -43%.
// smem [row 12][cc 12][px 68][2] fp32 (plane 11 = zeros for symmetric halves).
// Softmax: partial channel sums exchanged between h=0/h=1 via smem.
// ---------------------------------------------------------------------------
#define TX 64
#define TY 8
#define SWPX 68          // px cols x0-2 .. x0+65
#define SH 12
#define PLB 544          // bytes per (row,cc) plane = 68*8
#define RPB (NCCS*PLB)   // 6528 bytes per smem row (12 planes)
#define NCHK (SH*NCC*34) // 4488 16B cp.async chunks (planes 0..10)

template<bool FINAL>
__global__ void __launch_bounds__(256, 2) crf_iter(const float* __restrict__ unary,
                                                   const float* __restrict__ qin,
                                                   float* __restrict__ qout,
                                                   float* __restrict__ outp) {
    __shared__ float sq[SH*NCCS*SWPX*2];   // 78336 B
    int tx = threadIdx.x, ty = threadIdx.y;
    int b = blockIdx.z;
    int x0 = blockIdx.x * TX, y0 = blockIdx.y * TY;
    int tid = ty * 32 + tx;
    int lastbx = (int)gridDim.x - 1;
    bool bx0 = (blockIdx.x == 0), bxL = (blockIdx.x == lastbx);

    const float* qb = qin + (size_t)b * H * NCC * (W*2);
    uint32_t sbase = (uint32_t)__cvta_generic_to_shared(sq);

    // ---- fill planes 0..10: all 256 threads, incremental (row,cc,cx) ----
    {
        int idx = tid;
        int cx  = tid % 34;
        int pl  = tid / 34;
        int cc  = pl % NCC;
        int row = pl / NCC;
#pragma unroll
        for (int it = 0; it < 18; it++) {
            if (idx < NCHK) {
                bool skip = (bx0 && cx == 0) || (bxL && cx == 33);
                if (!skip) {
                    int gy = reflect_idx(y0 + row - 2, H);
                    const float* src = qb + ((size_t)gy*NCC + cc)*(W*2)
                                     + (x0 - 2)*2 + cx*4;
                    uint32_t dst = sbase + (uint32_t)(row*RPB + cc*PLB + cx*16);
                    asm volatile("cp.async.cg.shared.global [%0], [%1], 16;"
                                 :: "r"(dst), "l"(src));
                }
            }
            idx += 256;
            cx += 18; int cinc = 7;
            if (cx >= 34) { cx -= 34; cinc = 8; }
            cc += cinc;
            if (cc >= NCC) { cc -= NCC; row++; }
        }
        asm volatile("cp.async.commit_group;");
    }
    // zero pad plane (cc = 11)
    for (int idx = tid; idx < SH*34; idx += 256) {
        int prow = idx / 34, pcx = idx % 34;
        float4 z; z.x = 0.f; z.y = 0.f; z.z = 0.f; z.w = 0.f;
        *reinterpret_cast<float4*>(
            reinterpret_cast<char*>(sq) + prow*RPB + 11*PLB + pcx*16) = z;
    }
    // boundary reflect fix-ups
    if ((bx0 || bxL) && tid < SH*NCC) {
        int row = tid / NCC, cc = tid % NCC;
        int gy = reflect_idx(y0 + row - 2, H);
        const float* pl = qb + ((size_t)gy*NCC + cc)*(W*2);
        char* base = reinterpret_cast<char*>(sq) + row*RPB + cc*PLB;
        if (bx0) {
            float2 v0 = *reinterpret_cast<const float2*>(pl + 2*2);
            float2 v1 = *reinterpret_cast<const float2*>(pl + 1*2);
            *reinterpret_cast<float2*>(base)     = v0;
            *reinterpret_cast<float2*>(base + 8) = v1;
        }
        if (bxL) {
            float2 v0 = *reinterpret_cast<const float2*>(pl + 510*2);
            float2 v1 = *reinterpret_cast<const float2*>(pl + 509*2);
            *reinterpret_cast<float2*>(base + 66*8) = v0;
            *reinterpret_cast<float2*>(base + 67*8) = v1;
        }
    }
    asm volatile("cp.async.wait_group 0;" ::: "memory");
    __syncthreads();

    int r  = ty & 3;          // row pair index
    int h  = ty >> 2;         // channel half
    int ccb = h * 6;
    int px0 = x0 + 2*tx;
    int gy0 = y0 + 2*r;

    unsigned long long a00[6], a01[6], a10[6], a11[6];
#pragma unroll
    for (int j = 0; j < 6; j++) { a00[j]=0ULL; a01[j]=0ULL; a10[j]=0ULL; a11[j]=0ULL; }

    const __half* wp0 = g_wch + (size_t)b*HW + (size_t)gy0*W + px0;
    const __half* wp1 = wp0 + W;
    const char* sb = reinterpret_cast<const char*>(sq);

#pragma unroll
    for (int dy6 = 0; dy6 < 6; dy6++) {
        unsigned long long C00[5], C01[5], C10[5], C11[5];
        if (dy6 < 5) {
#pragma unroll
            for (int k = 0; k < 5; k++) {
                float2 f = __half22float2(*reinterpret_cast<const __half2*>(
                    wp0 + (size_t)(dy6*5 + k)*NBHW));
                C00[k] = pk2(f.x, f.x); C01[k] = pk2(f.y, f.y);
            }
        }
        if (dy6 >= 1) {
#pragma unroll
            for (int k = 0; k < 5; k++) {
                float2 f = __half22float2(*reinterpret_cast<const __half2*>(
                    wp1 + (size_t)((dy6-1)*5 + k)*NBHW));
                C10[k] = pk2(f.x, f.x); C11[k] = pk2(f.y, f.y);
            }
        }
        const char* rb = sb + (2*r + dy6)*RPB + ccb*PLB + tx*16;
#pragma unroll
        for (int j = 0; j < 6; j++) {
            const char* a = rb + j*PLB;
            ulonglong2 w01 = *reinterpret_cast<const ulonglong2*>(a);
            ulonglong2 w23 = *reinterpret_cast<const ulonglong2*>(a + 16);
            ulonglong2 w45 = *reinterpret_cast<const ulonglong2*>(a + 32);
            if (dy6 < 5) {
                FMA2(a00[j], C00[0], w01.x); FMA2(a00[j], C00[1], w01.y);
                FMA2(a00[j], C00[2], w23.x); FMA2(a00[j], C00[3], w23.y);
                FMA2(a00[j], C00[4], w45.x);
                FMA2(a01[j], C01[0], w01.y); FMA2(a01[j], C01[1], w23.x);
                FMA2(a01[j], C01[2], w23.y); FMA2(a01[j], C01[3], w45.x);
                FMA2(a01[j], C01[4], w45.y);
            }
            if (dy6 >= 1) {
                FMA2(a10[j], C10[0], w01.x); FMA2(a10[j], C10[1], w01.y);
                FMA2(a10[j], C10[2], w23.x); FMA2(a10[j], C10[3], w23.y);
                FMA2(a10[j], C10[4], w45.x);
                FMA2(a11[j], C11[0], w01.y); FMA2(a11[j], C11[1], w23.x);
                FMA2(a11[j], C11[2], w23.y); FMA2(a11[j], C11[3], w45.x);
                FMA2(a11[j], C11[4], w45.y);
            }
        }
    }

    // ---- epilogue: e = exp(unary - F), partial sums per pixel ----
    const float* ub0 = unary + (size_t)b*NC*HW + (size_t)gy0*W + px0;
    const float* ub1 = ub0 + W;
    float s00 = 0.f, s01 = 0.f, s10 = 0.f, s11 = 0.f;
#pragma unroll
    for (int j = 0; j < 6; j++) {
        int cc = ccb + j;
        int ch0 = 2*cc, ch1 = ch0 + 1;
        float f00x,f00y, f01x,f01y, f10x,f10y, f11x,f11y;
        upk2(f00x, f00y, a00[j]); upk2(f01x, f01y, a01[j]);
        upk2(f10x, f10y, a10[j]); upk2(f11x, f11y, a11[j]);
        float e00x=0.f, e00y=0.f, e01x=0.f, e01y=0.f;
        float e10x=0.f, e10y=0.f, e11x=0.f, e11y=0.f;
        if (ch0 < NC) {
            float2 uA0 = *reinterpret_cast<const float2*>(ub0 + (size_t)ch0*HW);
            float2 uA1 = *reinterpret_cast<const float2*>(ub1 + (size_t)ch0*HW);
            e00x = __expf(uA0.x - f00x);
            e01x = __expf(uA0.y - f01x);
            e10x = __expf(uA1.x - f10x);
            e11x = __expf(uA1.y - f11x);
        }
        if (ch1 < NC) {
            float2 uB0 = *reinterpret_cast<const float2*>(ub0 + (size_t)ch1*HW);
            float2 uB1 = *reinterpret_cast<const float2*>(ub1 + (size_t)ch1*HW);
            e00y = __expf(uB0.x - f00y);
            e01y = __expf(uB0.y - f01y);
            e10y = __expf(uB1.x - f10y);
            e11y = __expf(uB1.y - f11y);
        }
        a00[j] = pk2(e00x, e00y); a01[j] = pk2(e01x, e01y);
        a10[j] = pk2(e10x, e10y); a11[j] = pk2(e11x, e11y);
        s00 += e00x + e00y; s01 += e01x + e01y;
        s10 += e10x + e10y; s11 += e11x + e11y;
    }

    // ---- cross-half partial-sum exchange (reuse sq) ----
    __syncthreads();   // all stencil smem reads complete
    {
        float4* part = reinterpret_cast<float4*>(sq);
        float4 v; v.x = s00; v.y = s01; v.z = s10; v.w = s11;
        part[(r*32 + tx)*2 + h] = v;
    }
    __syncthreads();
    {
        const float4* part = reinterpret_cast<const float4*>(sq);
        float4 o = part[(r*32 + tx)*2 + (h ^ 1)];
        s00 += o.x; s01 += o.y; s10 += o.z; s11 += o.w;
    }
    float i00 = 1.f/s00, i01 = 1.f/s01, i10 = 1.f/s10, i11 = 1.f/s11;

    if (FINAL) {
        float* op0 = outp + (size_t)b*NC*HW + (size_t)gy0*W + px0;
#pragma unroll
        for (int j = 0; j < 6; j++) {
            int cc = ccb + j;
            int ch0 = 2*cc, ch1 = ch0 + 1;
            float e00x,e00y, e01x,e01y, e10x,e10y, e11x,e11y;
            upk2(e00x, e00y, a00[j]); upk2(e01x, e01y, a01[j]);
            upk2(e10x, e10y, a10[j]); upk2(e11x, e11y, a11[j]);
            if (ch0 < NC) {
                float2 v0; v0.x = e00x*i00; v0.y = e01x*i01;
                *reinterpret_cast<float2*>(op0 + (size_t)ch0*HW) = v0;
                float2 v1; v1.x = e10x*i10; v1.y = e11x*i11;
                *reinterpret_cast<float2*>(op0 + (size_t)ch0*HW + W) = v1;
            }
            if (ch1 < NC) {
                float2 v0; v0.x = e00y*i00; v0.y = e01y*i01;
                *reinterpret_cast<float2*>(op0 + (size_t)ch1*HW) = v0;
                float2 v1; v1.x = e10y*i10; v1.y = e11y*i11;
                *reinterpret_cast<float2*>(op0 + (size_t)ch1*HW + W) = v1;
            }
        }
    } else {
        unsigned long long I00 = pk2(i00,i00), I01 = pk2(i01,i01);
        unsigned long long I10 = pk2(i10,i10), I11 = pk2(i11,i11);
        float* q0 = qout + (size_t)b*H*NCC*(W*2) + ((size_t)gy0*NCC)*(W*2) + px0*2;
        float* q1 = q0 + NCC*(W*2);
#pragma unroll
        for (int j = 0; j < 6; j++) {
            int cc = ccb + j;
            if (cc < NCC) {
                ulonglong2 st0;
                MUL2(st0.x, a00[j], I00);
                MUL2(st0.y, a01[j], I01);
                *reinterpret_cast<ulonglong2*>(q0 + cc*(W*2)) = st0;
                ulonglong2 st1;
                MUL2(st1.x, a10[j], I10);
                MUL2(st1.y, a11[j], I11);
                *reinterpret_cast<ulonglong2*>(q1 + cc*(W*2)) = st1;
            }
        }
    }
}

// ---------------------------------------------------------------------------
extern "C" void kernel_launch(void* const* d_in, const int* in_sizes, int n_in,
                              void* d_out, int out_size) {
    const float *unary = nullptr, *image = nullptr, *edges = nullptr;
    for (int i = 0; i < n_in; i++) {
        if      (in_sizes[i] == NB*NC*HW) unary = (const float*)d_in[i];
        else if (in_sizes[i] == NB*3*HW)  image = (const float*)d_in[i];
        else if (in_sizes[i] == NB*HW)    edges = (const float*)d_in[i];
    }
    float* out = (float*)d_out;

    float *qA = nullptr, *qB = nullptr;
    cudaGetSymbolAddress((void**)&qA, g_qA);
    cudaGetSymbolAddress((void**)&qB, g_qB);

    init_softmax<<<(NPIX + 255)/256, 256>>>(unary, qA);
    compute_weights<<<dim3(W/32, H/8, NB), dim3(32, 8)>>>(image, edges);

    dim3 gi(W/TX, H/TY, NB), bi(32, 8);
    const float* cur = qA;
    for (int it = 0; it < 9; it++) {
        float* dst = (cur == qA) ? qB : qA;
        crf_iter<false><<<gi, bi>>>(unary, cur, dst, nullptr);
        cur = dst;
    }
    crf_iter<true><<<gi, bi>>>(unary, cur, nullptr, out);
}

// round 14
// speedup vs baseline: 1.0221x; 1.0221x over previous
#include <cuda_runtime.h>
#include <cuda_fp16.h>
#include <cstdint>

#define H 512
#define W 512
#define HW (H*W)
#define NB 2
#define NC 21
#define NCC 11           // channel pairs (ch20 paired with zero pad)
#define NPIX (NB*HW)
#define NTAP 25
#define NBHW (NB*HW)

// q buffers: pair-planar [b][y][cc][x][2] fp16; coefs planar fp16.
// Whole working set (q 46MB + coef 26MB + unary 44MB) fits in L2 (126MB).
__device__ __half g_qA[(size_t)NB*H*NCC*W*2];
__device__ __half g_qB[(size_t)NB*H*NCC*W*2];
__device__ __half g_wch[NTAP*NB*HW];

__device__ __forceinline__ int reflect_idx(int i, int n) {
    if (i < 0) i = -i;
    if (i >= n) i = 2*n - 2 - i;
    return i;
}

__device__ __forceinline__ unsigned long long pk2(float lo, float hi) {
    unsigned long long r;
    asm("mov.b64 %0, {%1, %2};" : "=l"(r) : "f"(lo), "f"(hi));
    return r;
}
__device__ __forceinline__ void upk2(float& lo, float& hi, unsigned long long v) {
    asm("mov.b64 {%0, %1}, %2;" : "=f"(lo), "=f"(hi) : "l"(v));
}
#define FMA2(acc, a, b) \
    asm("fma.rn.f32x2 %0, %1, %2, %0;" : "+l"(acc) : "l"(a), "l"(b))

// ---------------------------------------------------------------------------
// Kernel 1: q0 = softmax(unary), written pair-planar fp16
// ---------------------------------------------------------------------------
__global__ void __launch_bounds__(256) init_softmax(const float* __restrict__ unary,
                                                    __half* __restrict__ q) {
    int idx = blockIdx.x * 256 + threadIdx.x;
    if (idx >= NPIX) return;
    int b = idx / HW, pix = idx % HW;
    int y = pix / W, x = pix % W;
    const float* u = unary + (size_t)b * NC * HW + pix;
    float e[NC];
    float s = 0.f;
#pragma unroll
    for (int c = 0; c < NC; c++) { e[c] = __expf(u[c*HW]); s += e[c]; }
    float inv = 1.f / s;
    __half* qr = q + ((size_t)(b*H + y)*NCC)*(W*2) + x*2;
#pragma unroll
    for (int cc = 0; cc < 10; cc++) {
        *reinterpret_cast<__half2*>(qr + cc*(W*2)) =
            __floats2half2_rn(e[2*cc]*inv, e[2*cc+1]*inv);
    }
    *reinterpret_cast<__half2*>(qr + 10*(W*2)) = __floats2half2_rn(e[20]*inv, 0.f);
}

// ---------------------------------------------------------------------------
// Kernel 2: combined coefficients (fp16, planar SoA [tap][b][y][x])
// ---------------------------------------------------------------------------
__global__ void __launch_bounds__(256) compute_weights(const float* __restrict__ image,
                                                       const float* __restrict__ edges) {
    __shared__ float sg[4][12][36];
    int tx = threadIdx.x, ty = threadIdx.y;
    int b = blockIdx.z;
    int x0 = blockIdx.x * 32, y0 = blockIdx.y * 8;
    int tid = ty * 32 + tx;

    for (int idx = tid; idx < 4*12*36; idx += 256) {
        int ch = idx / (12*36);
        int r  = idx % (12*36);
        int ry = r / 36, sx = r % 36;
        int gy = reflect_idx(y0 + ry - 2, H);
        int gx = reflect_idx(x0 + sx - 2, W);
        float v;
        if (ch < 3) v = image[((size_t)(b*3 + ch))*HW + gy*W + gx];
        else        v = edges[(size_t)b*HW + gy*W + gx];
        sg[ch][ry][sx] = v;
    }
    __syncthreads();

    float sp[5], g2[5];
    {
        float s = 0.f;
#pragma unroll
        for (int i = 0; i < 5; i++) {
            float x = (float)(i - 2);
            sp[i] = __expf(-x*x * 0.02f);
            float g = __expf(-2.f * x*x);
            g2[i] = g; s += g;
        }
        float inv = 1.f / s;
#pragma unroll
        for (int i = 0; i < 5; i++) g2[i] *= inv;
    }

    int ry = ty + 2, rx = tx + 2;
    float cr = sg[0][ry][rx], cg = sg[1][ry][rx], cb = sg[2][ry][rx], ce = sg[3][ry][rx];

    float wr[NTAP], we[NTAP];
    float sr = 0.f, se = 0.f;
#pragma unroll
    for (int dy = 0; dy < 5; dy++) {
#pragma unroll
        for (int dx = 0; dx < 5; dx++) {
            int t = dy*5 + dx;
            float d = fabsf(sg[0][ry+dy-2][rx+dx-2] - cr)
                    + fabsf(sg[1][ry+dy-2][rx+dx-2] - cg)
                    + fabsf(sg[2][ry+dy-2][rx+dx-2] - cb);
            float s2 = sp[dy] * sp[dx];
            float w  = s2 * __expf(-2.f * d * d);
            wr[t] = w; sr += w;
            float de = fabsf(sg[3][ry+dy-2][rx+dx-2] - ce);
            float w2 = s2 * __expf(-2.f * de * de);
            we[t] = w2; se += w2;
        }
    }
    float isr = 1.f / sr, ise = 1.f / se;
    int pix = b*HW + (y0 + ty)*W + (x0 + tx);
#pragma unroll
    for (int dy = 0; dy < 5; dy++) {
#pragma unroll
        for (int dx = 0; dx < 5; dx++) {
            int t = dy*5 + dx;
            g_wch[t*(NB*HW) + pix] = __float2half(g2[dy]*g2[dx] + wr[t]*isr + we[t]*ise);
        }
    }
}

// ---------------------------------------------------------------------------
// Kernel 3: one CRF iteration, pair-planar.
// Tile 64x8, block (32,8)=256 thr, 2 px/thread, 3 CTAs/SM.
// q fp16 in GLOBAL (L2-resident working set); fp32 in SMEM (convert at fill:
// LDG.64 fp16 -> 4xF2F -> STS.128). Inner loop: 3xLDS.128 + 10xFFMA2, no cvt.
// ---------------------------------------------------------------------------
#define TX 64
#define TY 8
#define SWPX 68          // px cols x0-2 .. x0+65
#define SH 12
#define PLB 544          // bytes per (row,cc) smem plane = 68*8
#define RPB (NCC*PLB)    // 5984 bytes per smem row
#define NCHK (SH*NCC*34) // 4488 chunks (2 px each)

template<bool FINAL>
__global__ void __launch_bounds__(256, 3) crf_iter(const float* __restrict__ unary,
                                                   const __half* __restrict__ qin,
                                                   __half* __restrict__ qout,
                                                   float* __restrict__ outp) {
    __shared__ float sq[SH*NCC*SWPX*2];   // 71808 B
    int tx = threadIdx.x, ty = threadIdx.y;
    int b = blockIdx.z;
    int x0 = blockIdx.x * TX, y0 = blockIdx.y * TY;
    int tid = ty * 32 + tx;
    int lastbx = (int)gridDim.x - 1;
    bool bx0 = (blockIdx.x == 0), bxL = (blockIdx.x == lastbx);

    const __half* qb = qin + (size_t)b * H * NCC * (W*2);

    // ---- fill: all 256 threads; chunk = 2 px (8B fp16 -> 16B fp32 smem) ----
    {
        int idx = tid;
        int cx  = tid % 34;
        int pl  = tid / 34;
        int cc  = pl % NCC;
        int row = pl / NCC;
#pragma unroll
        for (int it = 0; it < 18; it++) {
            if (idx < NCHK) {
                bool skip = (bx0 && cx == 0) || (bxL && cx == 33);
                if (!skip) {
                    int gy = reflect_idx(y0 + row - 2, H);
                    const __half* src = qb + ((size_t)gy*NCC + cc)*(W*2)
                                      + (x0 - 2)*2 + cx*4;
                    __half2 h0 = *reinterpret_cast<const __half2*>(src);
                    __half2 h1 = *reinterpret_cast<const __half2*>(src + 2);
                    float2 f0 = __half22float2(h0);
                    float2 f1 = __half22float2(h1);
                    float4 v; v.x = f0.x; v.y = f0.y; v.z = f1.x; v.w = f1.y;
                    *reinterpret_cast<float4*>(
                        reinterpret_cast<char*>(sq) + row*RPB + cc*PLB + cx*16) = v;
                }
            }
            idx += 256;
            cx += 18; int cinc = 7;
            if (cx >= 34) { cx -= 34; cinc = 8; }
            cc += cinc;
            if (cc >= NCC) { cc -= NCC; row++; }
        }
    }
    // boundary reflect fix-ups
    if ((bx0 || bxL) && tid < SH*NCC) {
        int row = tid / NCC, cc = tid % NCC;
        int gy = reflect_idx(y0 + row - 2, H);
        const __half* pl = qb + ((size_t)gy*NCC + cc)*(W*2);
        char* base = reinterpret_cast<char*>(sq) + row*RPB + cc*PLB;
        if (bx0) {
            float2 v0 = __half22float2(*reinterpret_cast<const __half2*>(pl + 2*2));
            float2 v1 = __half22float2(*reinterpret_cast<const __half2*>(pl + 1*2));
            *reinterpret_cast<float2*>(base)     = v0;
            *reinterpret_cast<float2*>(base + 8) = v1;
        }
        if (bxL) {
            float2 v0 = __half22float2(*reinterpret_cast<const __half2*>(pl + 510*2));
            float2 v1 = __half22float2(*reinterpret_cast<const __half2*>(pl + 509*2));
            *reinterpret_cast<float2*>(base + 66*8) = v0;
            *reinterpret_cast<float2*>(base + 67*8) = v1;
        }
    }
    __syncthreads();

    int px0 = x0 + 2*tx;
    int gy  = y0 + ty;

    unsigned long long acc0[NCC], acc1[NCC];
#pragma unroll
    for (int cc = 0; cc < NCC; cc++) { acc0[cc] = 0ULL; acc1[cc] = 0ULL; }

    int wbase = b*HW + gy*W + px0;
    const char* sb = reinterpret_cast<const char*>(sq);

#pragma unroll
    for (int dy = 0; dy < 5; dy++) {
        const __half* wp = g_wch + (size_t)(dy*5)*NBHW + wbase;
        float2 c0 = __half22float2(*reinterpret_cast<const __half2*>(wp));
        float2 c1 = __half22float2(*reinterpret_cast<const __half2*>(wp +   (size_t)NBHW));
        float2 c2 = __half22float2(*reinterpret_cast<const __half2*>(wp + 2*(size_t)NBHW));
        float2 c3 = __half22float2(*reinterpret_cast<const __half2*>(wp + 3*(size_t)NBHW));
        float2 c4 = __half22float2(*reinterpret_cast<const __half2*>(wp + 4*(size_t)NBHW));
        unsigned long long CC00 = pk2(c0.x, c0.x), CC10 = pk2(c0.y, c0.y);
        unsigned long long CC01 = pk2(c1.x, c1.x), CC11 = pk2(c1.y, c1.y);
        unsigned long long CC02 = pk2(c2.x, c2.x), CC12 = pk2(c2.y, c2.y);
        unsigned long long CC03 = pk2(c3.x, c3.x), CC13 = pk2(c3.y, c3.y);
        unsigned long long CC04 = pk2(c4.x, c4.x), CC14 = pk2(c4.y, c4.y);

        const char* rb = sb + (ty + dy)*RPB + tx*16;   // window cols 2tx..2tx+5
#pragma unroll
        for (int cc = 0; cc < NCC; cc++) {
            const char* a = rb + cc*PLB;
            ulonglong2 w01 = *reinterpret_cast<const ulonglong2*>(a);       // cols 0,1
            ulonglong2 w23 = *reinterpret_cast<const ulonglong2*>(a + 16);  // cols 2,3
            ulonglong2 w45 = *reinterpret_cast<const ulonglong2*>(a + 32);  // cols 4,5
            FMA2(acc0[cc], CC00, w01.x);
            FMA2(acc0[cc], CC01, w01.y);
            FMA2(acc0[cc], CC02, w23.x);
            FMA2(acc0[cc], CC03, w23.y);
            FMA2(acc0[cc], CC04, w45.x);
            FMA2(acc1[cc], CC10, w01.y);
            FMA2(acc1[cc], CC11, w23.x);
            FMA2(acc1[cc], CC12, w23.y);
            FMA2(acc1[cc], CC13, w45.x);
            FMA2(acc1[cc], CC14, w45.y);
        }
    }

    // ---- epilogue: q = softmax(unary - F) ----
    const float* ub = unary + (size_t)b * NC * HW + gy*W + px0;
    float s0 = 0.f, s1 = 0.f;
#pragma unroll
    for (int cc = 0; cc < NCC; cc++) {
        float fa, fb, ga, gb;
        upk2(fa, fb, acc0[cc]);   // px0: ch 2cc, 2cc+1
        upk2(ga, gb, acc1[cc]);   // px1
        float2 uA = *reinterpret_cast<const float2*>(ub + (size_t)(2*cc)*HW);
        float e00 = __expf(uA.x - fa);
        float e10 = __expf(uA.y - ga);
        float e01 = 0.f, e11 = 0.f;
        if (cc < 10) {
            float2 uB = *reinterpret_cast<const float2*>(ub + (size_t)(2*cc+1)*HW);
            e01 = __expf(uB.x - fb);
            e11 = __expf(uB.y - gb);
        }
        acc0[cc] = pk2(e00, e01);
        acc1[cc] = pk2(e10, e11);
        s0 += e00 + e01;
        s1 += e10 + e11;
    }
    float i0 = 1.f / s0, i1 = 1.f / s1;

    if (FINAL) {
        float* op = outp + (size_t)b * NC * HW + gy*W + px0;
#pragma unroll
        for (int cc = 0; cc < NCC; cc++) {
            float e00, e01, e10, e11;
            upk2(e00, e01, acc0[cc]);
            upk2(e10, e11, acc1[cc]);
            float2 vA; vA.x = e00*i0; vA.y = e10*i1;
            *reinterpret_cast<float2*>(op + (size_t)(2*cc)*HW) = vA;
            if (cc < 10) {
                float2 vB; vB.x = e01*i0; vB.y = e11*i1;
                *reinterpret_cast<float2*>(op + (size_t)(2*cc+1)*HW) = vB;
            }
        }
    } else {
        __half* qo = qout + (size_t)b * H * NCC * (W*2)
                          + ((size_t)gy*NCC)*(W*2) + px0*2;
#pragma unroll
        for (int cc = 0; cc < NCC; cc++) {
            float e00, e01, e10, e11;
            upk2(e00, e01, acc0[cc]);   // px0 (ch0,ch1)
            upk2(e10, e11, acc1[cc]);   // px1 (ch0,ch1)
            __half2 h0 = __floats2half2_rn(e00*i0, e01*i0);
            __half2 h1 = __floats2half2_rn(e10*i1, e11*i1);
            uint2 st;
            st.x = *reinterpret_cast<uint32_t*>(&h0);
            st.y = *reinterpret_cast<uint32_t*>(&h1);
            *reinterpret_cast<uint2*>(qo + cc*(W*2)) = st;
        }
    }
}

// ---------------------------------------------------------------------------
extern "C" void kernel_launch(void* const* d_in, const int* in_sizes, int n_in,
                              void* d_out, int out_size) {
    const float *unary = nullptr, *image = nullptr, *edges = nullptr;
    for (int i = 0; i < n_in; i++) {
        if      (in_sizes[i] == NB*NC*HW) unary = (const float*)d_in[i];
        else if (in_sizes[i] == NB*3*HW)  image = (const float*)d_in[i];
        else if (in_sizes[i] == NB*HW)    edges = (const float*)d_in[i];
    }
    float* out = (float*)d_out;

    __half *qA = nullptr, *qB = nullptr;
    cudaGetSymbolAddress((void**)&qA, g_qA);
    cudaGetSymbolAddress((void**)&qB, g_qB);

    init_softmax<<<(NPIX + 255)/256, 256>>>(unary, qA);
    compute_weights<<<dim3(W/32, H/8, NB), dim3(32, 8)>>>(image, edges);

    dim3 gi(W/TX, H/TY, NB), bi(32, 8);
    const __half* cur = qA;
    for (int it = 0; it < 9; it++) {
        __half* dst = (cur == qA) ? qB : qA;
        crf_iter<false><<<gi, bi>>>(unary, cur, dst, nullptr);
        cur = dst;
    }
    crf_iter<true><<<gi, bi>>>(unary, cur, nullptr, out);
}

// round 15
// speedup vs baseline: 1.0854x; 1.0619x over previous
#include <cuda_runtime.h>
#include <cuda_fp16.h>
#include <cstdint>

#define H 512
#define W 512
#define HW (H*W)
#define NB 2
#define NC 21
#define NCC 11           // channel pairs (ch20 paired with zero pad)
#define NPIX (NB*HW)
#define NTAP 25
#define NBHW (NB*HW)

// q buffers: pair-planar layout [b][y][cc][x][2] fp32; coefs planar fp16
__device__ float  g_qA[(size_t)NB*H*NCC*W*2];
__device__ float  g_qB[(size_t)NB*H*NCC*W*2];
__device__ __half g_wch[NTAP*NB*HW];

__device__ __forceinline__ int reflect_idx(int i, int n) {
    if (i < 0) i = -i;
    if (i >= n) i = 2*n - 2 - i;
    return i;
}

__device__ __forceinline__ unsigned long long pk2(float lo, float hi) {
    unsigned long long r;
    asm("mov.b64 %0, {%1, %2};" : "=l"(r) : "f"(lo), "f"(hi));
    return r;
}
__device__ __forceinline__ void upk2(float& lo, float& hi, unsigned long long v) {
    asm("mov.b64 {%0, %1}, %2;" : "=f"(lo), "=f"(hi) : "l"(v));
}
#define FMA2(acc, a, b) \
    asm("fma.rn.f32x2 %0, %1, %2, %0;" : "+l"(acc) : "l"(a), "l"(b))
#define MUL2(out, a, b) \
    asm("mul.rn.f32x2 %0, %1, %2;" : "=l"(out) : "l"(a), "l"(b))

// ---------------------------------------------------------------------------
// Kernel 1: q0 = softmax(unary), written pair-planar
// ---------------------------------------------------------------------------
__global__ void __launch_bounds__(256) init_softmax(const float* __restrict__ unary,
                                                    float* __restrict__ q) {
    int idx = blockIdx.x * 256 + threadIdx.x;
    if (idx >= NPIX) return;
    int b = idx / HW, pix = idx % HW;
    int y = pix / W, x = pix % W;
    const float* u = unary + (size_t)b * NC * HW + pix;
    float e[NC];
    float s = 0.f;
#pragma unroll
    for (int c = 0; c < NC; c++) { e[c] = __expf(u[c*HW]); s += e[c]; }
    float inv = 1.f / s;
    float* qr = q + ((size_t)(b*H + y)*NCC)*(W*2) + x*2;
#pragma unroll
    for (int cc = 0; cc < 10; cc++) {
        float2 v; v.x = e[2*cc]*inv; v.y = e[2*cc+1]*inv;
        *reinterpret_cast<float2*>(qr + cc*(W*2)) = v;
    }
    float2 v10; v10.x = e[20]*inv; v10.y = 0.f;
    *reinterpret_cast<float2*>(qr + 10*(W*2)) = v10;
}

// ---------------------------------------------------------------------------
// Kernel 2: combined coefficients (fp16, planar SoA [tap][b][y][x])
// ---------------------------------------------------------------------------
__global__ void __launch_bounds__(256) compute_weights(const float* __restrict__ image,
                                                       const float* __restrict__ edges) {
    __shared__ float sg[4][12][36];
    int tx = threadIdx.x, ty = threadIdx.y;
    int b = blockIdx.z;
    int x0 = blockIdx.x * 32, y0 = blockIdx.y * 8;
    int tid = ty * 32 + tx;

    for (int idx = tid; idx < 4*12*36; idx += 256) {
        int ch = idx / (12*36);
        int r  = idx % (12*36);
        int ry = r / 36, sx = r % 36;
        int gy = reflect_idx(y0 + ry - 2, H);
        int gx = reflect_idx(x0 + sx - 2, W);
        float v;
        if (ch < 3) v = image[((size_t)(b*3 + ch))*HW + gy*W + gx];
        else        v = edges[(size_t)b*HW + gy*W + gx];
        sg[ch][ry][sx] = v;
    }
    __syncthreads();

    float sp[5], g2[5];
    {
        float s = 0.f;
#pragma unroll
        for (int i = 0; i < 5; i++) {
            float x = (float)(i - 2);
            sp[i] = __expf(-x*x * 0.02f);
            float g = __expf(-2.f * x*x);
            g2[i] = g; s += g;
        }
        float inv = 1.f / s;
#pragma unroll
        for (int i = 0; i < 5; i++) g2[i] *= inv;
    }

    int ry = ty + 2, rx = tx + 2;
    float cr = sg[0][ry][rx], cg = sg[1][ry][rx], cb = sg[2][ry][rx], ce = sg[3][ry][rx];

    float wr[NTAP], we[NTAP];
    float sr = 0.f, se = 0.f;
#pragma unroll
    for (int dy = 0; dy < 5; dy++) {
#pragma unroll
        for (int dx = 0; dx < 5; dx++) {
            int t = dy*5 + dx;
            float d = fabsf(sg[0][ry+dy-2][rx+dx-2] - cr)
                    + fabsf(sg[1][ry+dy-2][rx+dx-2] - cg)
                    + fabsf(sg[2][ry+dy-2][rx+dx-2] - cb);
            float s2 = sp[dy] * sp[dx];
            float w  = s2 * __expf(-2.f * d * d);
            wr[t] = w; sr += w;
            float de = fabsf(sg[3][ry+dy-2][rx+dx-2] - ce);
            float w2 = s2 * __expf(-2.f * de * de);
            we[t] = w2; se += w2;
        }
    }
    float isr = 1.f / sr, ise = 1.f / se;
    int pix = b*HW + (y0 + ty)*W + (x0 + tx);
#pragma unroll
    for (int dy = 0; dy < 5; dy++) {
#pragma unroll
        for (int dx = 0; dx < 5; dx++) {
            int t = dy*5 + dx;
            g_wch[t*(NB*HW) + pix] = __float2half(g2[dy]*g2[dx] + wr[t]*isr + we[t]*ise);
        }
    }
}

// ---------------------------------------------------------------------------
// Kernel 3: one CRF iteration, pair-planar.
// Tile 32x16, block (16,16)=256 thr, 2 px/thread, 3 CTAs/SM.
// Taller tile: y-halo overhead 1.25x (vs 1.5x at 64x8) -> -12% fill traffic.
// smem [row 20][cc 11][px 36][2] fp32; inner loop 3xLDS.128 + 10xFFMA2.
// ---------------------------------------------------------------------------
#define TX 32
#define TY 16
#define SWPX 36          // px cols x0-2 .. x0+33
#define SH 20            // TY + 4
#define PLB 288          // bytes per (row,cc) plane = 36*8
#define RPB (NCC*PLB)    // 3168 bytes per smem row
#define NCHK (SH*NCC*18) // 3960 16B chunks (2 px each)

template<bool FINAL>
__global__ void __launch_bounds__(256, 3) crf_iter(const float* __restrict__ unary,
                                                   const float* __restrict__ qin,
                                                   float* __restrict__ qout,
                                                   float* __restrict__ outp) {
    __shared__ float sq[SH*NCC*SWPX*2];   // 63360 B
    int tx = threadIdx.x;                 // 0..15
    int ty = threadIdx.y;                 // 0..15
    int b = blockIdx.z;
    int x0 = blockIdx.x * TX, y0 = blockIdx.y * TY;
    int tid = ty * 16 + tx;
    int lastbx = (int)gridDim.x - 1;
    bool bx0 = (blockIdx.x == 0), bxL = (blockIdx.x == lastbx);

    const float* qb = qin + (size_t)b * H * NCC * (W*2);
    uint32_t sbase = (uint32_t)__cvta_generic_to_shared(sq);

    // ---- fill: all 256 threads, chunk idx = (row, cc, cx), incremental ----
    {
        int idx = tid;
        int cx  = tid % 18;
        int pl  = tid / 18;
        int cc  = pl % NCC;
        int row = pl / NCC;
#pragma unroll
        for (int it = 0; it < 16; it++) {
            if (idx < NCHK) {
                bool skip = (bx0 && cx == 0) || (bxL && cx == 17);
                if (!skip) {
                    int gy = reflect_idx(y0 + row - 2, H);
                    const float* src = qb + ((size_t)gy*NCC + cc)*(W*2)
                                     + (x0 - 2)*2 + cx*4;
                    uint32_t dst = sbase + (uint32_t)(row*RPB + cc*PLB + cx*16);
                    asm volatile("cp.async.cg.shared.global [%0], [%1], 16;"
                                 :: "r"(dst), "l"(src));
                }
            }
            idx += 256;
            // 256 = 14*18 + 4
            cx += 4; int pinc = 14;
            if (cx >= 18) { cx -= 18; pinc = 15; }
            cc += pinc;                        // pinc <= 15
            if (cc >= NCC) { cc -= NCC; row++; }
            if (cc >= NCC) { cc -= NCC; row++; }
        }
        asm volatile("cp.async.commit_group;");
    }
    // boundary reflect fix-ups (plain STS, one thread per (row,cc) plane)
    if ((bx0 || bxL) && tid < SH*NCC) {
        int row = tid / NCC, cc = tid % NCC;
        int gy = reflect_idx(y0 + row - 2, H);
        const float* pl = qb + ((size_t)gy*NCC + cc)*(W*2);
        char* base = reinterpret_cast<char*>(sq) + row*RPB + cc*PLB;
        if (bx0) {
            float2 v0 = *reinterpret_cast<const float2*>(pl + 2*2);   // x=-2 -> gx=2
            float2 v1 = *reinterpret_cast<const float2*>(pl + 1*2);   // x=-1 -> gx=1
            *reinterpret_cast<float2*>(base)     = v0;
            *reinterpret_cast<float2*>(base + 8) = v1;
        }
        if (bxL) {
            float2 v0 = *reinterpret_cast<const float2*>(pl + 510*2); // x=512 -> 510
            float2 v1 = *reinterpret_cast<const float2*>(pl + 509*2); // x=513 -> 509
            *reinterpret_cast<float2*>(base + 34*8) = v0;
            *reinterpret_cast<float2*>(base + 35*8) = v1;
        }
    }
    asm volatile("cp.async.wait_group 0;" ::: "memory");
    __syncthreads();

    int px0 = x0 + 2*tx;
    int gy  = y0 + ty;

    unsigned long long acc0[NCC], acc1[NCC];
#pragma unroll
    for (int cc = 0; cc < NCC; cc++) { acc0[cc] = 0ULL; acc1[cc] = 0ULL; }

    int wbase = b*HW + gy*W + px0;
    const char* sb = reinterpret_cast<const char*>(sq);

#pragma unroll
    for (int dy = 0; dy < 5; dy++) {
        const __half* wp = g_wch + (size_t)(dy*5)*NBHW + wbase;
        float2 c0 = __half22float2(*reinterpret_cast<const __half2*>(wp));
        float2 c1 = __half22float2(*reinterpret_cast<const __half2*>(wp +   (size_t)NBHW));
        float2 c2 = __half22float2(*reinterpret_cast<const __half2*>(wp + 2*(size_t)NBHW));
        float2 c3 = __half22float2(*reinterpret_cast<const __half2*>(wp + 3*(size_t)NBHW));
        float2 c4 = __half22float2(*reinterpret_cast<const __half2*>(wp + 4*(size_t)NBHW));
        unsigned long long CC00 = pk2(c0.x, c0.x), CC10 = pk2(c0.y, c0.y);
        unsigned long long CC01 = pk2(c1.x, c1.x), CC11 = pk2(c1.y, c1.y);
        unsigned long long CC02 = pk2(c2.x, c2.x), CC12 = pk2(c2.y, c2.y);
        unsigned long long CC03 = pk2(c3.x, c3.x), CC13 = pk2(c3.y, c3.y);
        unsigned long long CC04 = pk2(c4.x, c4.x), CC14 = pk2(c4.y, c4.y);

        const char* rb = sb + (ty + dy)*RPB + tx*16;   // window cols 2tx..2tx+5
#pragma unroll
        for (int cc = 0; cc < NCC; cc++) {
            const char* a = rb + cc*PLB;
            ulonglong2 w01 = *reinterpret_cast<const ulonglong2*>(a);       // cols 0,1
            ulonglong2 w23 = *reinterpret_cast<const ulonglong2*>(a + 16);  // cols 2,3
            ulonglong2 w45 = *reinterpret_cast<const ulonglong2*>(a + 32);  // cols 4,5
            FMA2(acc0[cc], CC00, w01.x);
            FMA2(acc0[cc], CC01, w01.y);
            FMA2(acc0[cc], CC02, w23.x);
            FMA2(acc0[cc], CC03, w23.y);
            FMA2(acc0[cc], CC04, w45.x);
            FMA2(acc1[cc], CC10, w01.y);
            FMA2(acc1[cc], CC11, w23.x);
            FMA2(acc1[cc], CC12, w23.y);
            FMA2(acc1[cc], CC13, w45.x);
            FMA2(acc1[cc], CC14, w45.y);
        }
    }

    // ---- epilogue: q = softmax(unary - F) ----
    const float* ub = unary + (size_t)b * NC * HW + gy*W + px0;
    float s0 = 0.f, s1 = 0.f;
#pragma unroll
    for (int cc = 0; cc < NCC; cc++) {
        float fa, fb, ga, gb;
        upk2(fa, fb, acc0[cc]);   // px0: ch 2cc, 2cc+1
        upk2(ga, gb, acc1[cc]);   // px1
        float2 uA = *reinterpret_cast<const float2*>(ub + (size_t)(2*cc)*HW);
        float e00 = __expf(uA.x - fa);
        float e10 = __expf(uA.y - ga);
        float e01 = 0.f, e11 = 0.f;
        if (cc < 10) {
            float2 uB = *reinterpret_cast<const float2*>(ub + (size_t)(2*cc+1)*HW);
            e01 = __expf(uB.x - fb);
            e11 = __expf(uB.y - gb);
        }
        acc0[cc] = pk2(e00, e01);
        acc1[cc] = pk2(e10, e11);
        s0 += e00 + e01;
        s1 += e10 + e11;
    }
    float i0 = 1.f / s0, i1 = 1.f / s1;

    if (FINAL) {
        float* op = outp + (size_t)b * NC * HW + gy*W + px0;
#pragma unroll
        for (int cc = 0; cc < NCC; cc++) {
            float e00, e01, e10, e11;
            upk2(e00, e01, acc0[cc]);
            upk2(e10, e11, acc1[cc]);
            float2 vA; vA.x = e00*i0; vA.y = e10*i1;
            *reinterpret_cast<float2*>(op + (size_t)(2*cc)*HW) = vA;
            if (cc < 10) {
                float2 vB; vB.x = e01*i0; vB.y = e11*i1;
                *reinterpret_cast<float2*>(op + (size_t)(2*cc+1)*HW) = vB;
            }
        }
    } else {
        unsigned long long I0 = pk2(i0, i0), I1 = pk2(i1, i1);
        float* qo = qout + (size_t)b * H * NCC * (W*2)
                         + ((size_t)gy*NCC)*(W*2) + px0*2;
#pragma unroll
        for (int cc = 0; cc < NCC; cc++) {
            ulonglong2 st;
            MUL2(st.x, acc0[cc], I0);   // px0 pair
            MUL2(st.y, acc1[cc], I1);   // px1 pair
            *reinterpret_cast<ulonglong2*>(qo + cc*(W*2)) = st;
        }
    }
}

// ---------------------------------------------------------------------------
extern "C" void kernel_launch(void* const* d_in, const int* in_sizes, int n_in,
                              void* d_out, int out_size) {
    const float *unary = nullptr, *image = nullptr, *edges = nullptr;
    for (int i = 0; i < n_in; i++) {
        if      (in_sizes[i] == NB*NC*HW) unary = (const float*)d_in[i];
        else if (in_sizes[i] == NB*3*HW)  image = (const float*)d_in[i];
        else if (in_sizes[i] == NB*HW)    edges = (const float*)d_in[i];
    }
    float* out = (float*)d_out;

    float *qA = nullptr, *qB = nullptr;
    cudaGetSymbolAddress((void**)&qA, g_qA);
    cudaGetSymbolAddress((void**)&qB, g_qB);

    init_softmax<<<(NPIX + 255)/256, 256>>>(unary, qA);
    compute_weights<<<dim3(W/32, H/8, NB), dim3(32, 8)>>>(image, edges);

    dim3 gi(W/TX, H/TY, NB), bi(16, 16);
    const float* cur = qA;
    for (int it = 0; it < 9; it++) {
        float* dst = (cur == qA) ? qB : qA;
        crf_iter<false><<<gi, bi>>>(unary, cur, dst, nullptr);
        cur = dst;
    }
    crf_iter<true><<<gi, bi>>>(unary, cur, nullptr, out);
}